// round 1
// baseline (speedup 1.0000x reference)
#include <cuda_runtime.h>
#include <cuda_bf16.h>
#include <stdint.h>

// Problem constants
#define TT 6
#define BB 8
#define CC 192
#define HH 112
#define WW 112
#define KK 3
#define H0 56
#define W0 56
#define HWPIX (HH*WW)          // 12544
#define PIX (H0*W0)            // 3136
#define NN (TT*KK)             // 18 nodes
#define CG 8                   // channels per block in streaming kernels

// Scratch (static device globals — no allocation)
__device__ uint8_t g_packed[BB*TT*PIX];      // [b][t][pix] bits: k0|k1<<1|k2<<2
__device__ float   g_feat[BB*NN*CC];          // node features [B][N][C]
__device__ float   g_outk[BB*NN*CC];          // GCN output    [B][N][C]

// ---------------------------------------------------------------------------
// Kernel 0: pack the 3 binary masks into one byte per 56x56 pixel
// gcn_masks: [B,T,K,56,56] int32
__global__ void pack_kernel(const int* __restrict__ masks) {
    int p = blockIdx.x * blockDim.x + threadIdx.x;   // over B*T*PIX
    if (p >= BB*TT*PIX) return;
    int pix = p % PIX;
    int bt  = p / PIX;                               // b*T + t
    const int* mp = masks + (size_t)bt * (KK*PIX) + pix;
    uint8_t v = (uint8_t)((mp[0] & 1) | ((mp[PIX] & 1) << 1) | ((mp[2*PIX] & 1) << 2));
    g_packed[p] = v;
}

// ---------------------------------------------------------------------------
// Kernel 1: masked adaptive pooling.
// feat[b,t,k,c] = sum_{h,w} x[t,b,c,h,w] * mask[b,t,k,h/2,w/2] / (H*W)
// block = (t*B+b, channel-group of CG), 256 threads, mask in smem.
__global__ __launch_bounds__(256) void pool_kernel(const float* __restrict__ x) {
    int tb = blockIdx.x;          // t*B + b
    int cg = blockIdx.y;          // channel group
    int t = tb / BB, b = tb % BB;

    __shared__ uint8_t msk[PIX];
    __shared__ float red[8][3];

    const uint8_t* src = g_packed + (size_t)(b*TT + t) * PIX;
    for (int i = threadIdx.x; i < PIX/4; i += blockDim.x)
        ((uint32_t*)msk)[i] = ((const uint32_t*)src)[i];
    __syncthreads();

    int warp = threadIdx.x >> 5, lane = threadIdx.x & 31;

    for (int cc = 0; cc < CG; cc++) {
        int c = cg * CG + cc;
        const float4* xp = (const float4*)(x + ((size_t)(t*BB + b)*CC + c) * HWPIX);
        float s0 = 0.f, s1 = 0.f, s2 = 0.f;
        for (int i4 = threadIdx.x; i4 < HWPIX/4; i4 += blockDim.x) {
            float4 v = xp[i4];
            int lin = i4 * 4;
            int h = lin / WW;
            int w = lin - h * WW;                 // multiple of 4
            int mb = (h >> 1) * W0 + (w >> 1);
            uint8_t m0 = msk[mb], m1 = msk[mb + 1];
            float p0 = v.x + v.y, p1 = v.z + v.w;
            s0 += p0 * (float)(m0 & 1)        + p1 * (float)(m1 & 1);
            s1 += p0 * (float)((m0 >> 1) & 1) + p1 * (float)((m1 >> 1) & 1);
            s2 += p0 * (float)((m0 >> 2) & 1) + p1 * (float)((m1 >> 2) & 1);
        }
        // warp reduce
        #pragma unroll
        for (int off = 16; off; off >>= 1) {
            s0 += __shfl_down_sync(0xFFFFFFFFu, s0, off);
            s1 += __shfl_down_sync(0xFFFFFFFFu, s1, off);
            s2 += __shfl_down_sync(0xFFFFFFFFu, s2, off);
        }
        if (lane == 0) { red[warp][0] = s0; red[warp][1] = s1; red[warp][2] = s2; }
        __syncthreads();
        if (threadIdx.x == 0) {
            float r0 = 0.f, r1 = 0.f, r2 = 0.f;
            #pragma unroll
            for (int w8 = 0; w8 < 8; w8++) { r0 += red[w8][0]; r1 += red[w8][1]; r2 += red[w8][2]; }
            const float inv = 1.0f / (float)HWPIX;
            size_t base = ((size_t)(b*TT + t) * KK) * CC + c;   // [B][T][K][C]
            g_feat[base]        = r0 * inv;
            g_feat[base + CC]   = r1 * inv;
            g_feat[base + 2*CC] = r2 * inv;
        }
        __syncthreads();
    }
}

// ---------------------------------------------------------------------------
// Kernel 2: the whole GCN chain per batch. 8 blocks x 192 threads.
// node [18,192] -> adj=softmax(node node^T); aaa=node W_emb^T;
// sup=aaa W_gcn; out = adj sup + b_gcn
__global__ __launch_bounds__(192) void gcn_kernel(const float* __restrict__ W_emb,
                                                  const float* __restrict__ W_gcn,
                                                  const float* __restrict__ b_gcn) {
    const int LD = 193;  // padded row stride (conflict-free)
    __shared__ float node_s[NN*LD];
    __shared__ float aaa_s[NN*LD];
    __shared__ float sup_s[NN*LD];
    __shared__ float adj_s[NN*NN];

    int b = blockIdx.x;
    int tid = threadIdx.x;     // 0..191

    const float* fb = g_feat + (size_t)b * NN * CC;
    for (int j = tid; j < NN*CC; j += 192)
        node_s[(j / CC) * LD + (j % CC)] = fb[j];
    __syncthreads();

    // Gram matrix: 324 pairs
    for (int p = tid; p < NN*NN; p += 192) {
        int n = p / NN, m = p % NN;
        float s = 0.f;
        #pragma unroll 4
        for (int c = 0; c < CC; c++)
            s += node_s[n*LD + c] * node_s[m*LD + c];
        adj_s[p] = s;
    }
    __syncthreads();

    // row softmax (one thread per row)
    if (tid < NN) {
        float mx = -1e30f;
        #pragma unroll
        for (int m = 0; m < NN; m++) mx = fmaxf(mx, adj_s[tid*NN + m]);
        float e[NN]; float sm = 0.f;
        #pragma unroll
        for (int m = 0; m < NN; m++) { e[m] = expf(adj_s[tid*NN + m] - mx); sm += e[m]; }
        float inv = 1.0f / sm;
        #pragma unroll
        for (int m = 0; m < NN; m++) adj_s[tid*NN + m] = e[m] * inv;
    }
    __syncthreads();

    int d = tid;  // 0..191 — output column owned by this thread

    // aaa[n][d] = sum_c node[n][c] * W_emb[d][c]
    {
        float acc[NN];
        #pragma unroll
        for (int n = 0; n < NN; n++) acc[n] = 0.f;
        const float* wr = W_emb + (size_t)d * CC;
        for (int c = 0; c < CC; c++) {
            float w = __ldg(&wr[c]);
            #pragma unroll
            for (int n = 0; n < NN; n++) acc[n] += node_s[n*LD + c] * w;
        }
        #pragma unroll
        for (int n = 0; n < NN; n++) aaa_s[n*LD + d] = acc[n];
    }
    __syncthreads();

    // sup[m][d] = sum_d2 aaa[m][d2] * W_gcn[d2][d]   (coalesced W_gcn reads)
    {
        float acc[NN];
        #pragma unroll
        for (int m = 0; m < NN; m++) acc[m] = 0.f;
        for (int d2 = 0; d2 < CC; d2++) {
            float w = __ldg(&W_gcn[(size_t)d2 * CC + d]);
            #pragma unroll
            for (int m = 0; m < NN; m++) acc[m] += aaa_s[m*LD + d2] * w;
        }
        #pragma unroll
        for (int m = 0; m < NN; m++) sup_s[m*LD + d] = acc[m];
    }
    __syncthreads();

    // out[n][d] = b_gcn[d] + sum_m adj[n][m] * sup[m][d]
    {
        float bg = __ldg(&b_gcn[d]);
        #pragma unroll
        for (int n = 0; n < NN; n++) {
            float o = bg;
            #pragma unroll
            for (int m = 0; m < NN; m++) o += adj_s[n*NN + m] * sup_s[m*LD + d];
            g_outk[((size_t)b * NN + n) * CC + d] = o;
        }
    }
}

// ---------------------------------------------------------------------------
// Kernel 3: residual scatter + add.
// out[t,b,c,h,w] = x[t,b,c,h,w] + sum_k outk[b,t,k,c] * mask[b,t,k,h/2,w/2]
__global__ __launch_bounds__(256) void scatter_kernel(const float* __restrict__ x,
                                                      float* __restrict__ out) {
    int tb = blockIdx.x;          // t*B + b
    int cg = blockIdx.y;
    int t = tb / BB, b = tb % BB;

    __shared__ uint8_t msk[PIX];
    const uint8_t* src = g_packed + (size_t)(b*TT + t) * PIX;
    for (int i = threadIdx.x; i < PIX/4; i += blockDim.x)
        ((uint32_t*)msk)[i] = ((const uint32_t*)src)[i];
    __syncthreads();

    for (int cc = 0; cc < CG; cc++) {
        int c = cg * CG + cc;
        size_t base = ((size_t)(b*TT + t) * KK) * CC + c;   // [B][T][K][C]
        float r0 = g_outk[base];
        float r1 = g_outk[base + CC];
        float r2 = g_outk[base + 2*CC];

        size_t plane = ((size_t)(t*BB + b)*CC + c) * HWPIX;
        const float4* xp = (const float4*)(x + plane);
        float4*       op = (float4*)(out + plane);

        for (int i4 = threadIdx.x; i4 < HWPIX/4; i4 += blockDim.x) {
            float4 v = xp[i4];
            int lin = i4 * 4;
            int h = lin / WW;
            int w = lin - h * WW;
            int mb = (h >> 1) * W0 + (w >> 1);
            uint8_t m0 = msk[mb], m1 = msk[mb + 1];
            float c0 = ((m0 & 1) ? r0 : 0.f) + ((m0 & 2) ? r1 : 0.f) + ((m0 & 4) ? r2 : 0.f);
            float c1 = ((m1 & 1) ? r0 : 0.f) + ((m1 & 2) ? r1 : 0.f) + ((m1 & 4) ? r2 : 0.f);
            float4 o;
            o.x = v.x + c0; o.y = v.y + c0;
            o.z = v.z + c1; o.w = v.w + c1;
            op[i4] = o;
        }
    }
}

// ---------------------------------------------------------------------------
extern "C" void kernel_launch(void* const* d_in, const int* in_sizes, int n_in,
                              void* d_out, int out_size) {
    const float* x      = (const float*)d_in[0];
    const int*   masks  = (const int*)  d_in[1];
    const float* W_emb  = (const float*)d_in[2];
    const float* W_gcn  = (const float*)d_in[3];
    const float* b_gcn  = (const float*)d_in[4];
    float* out = (float*)d_out;

    // 0: pack masks (B*T*PIX threads)
    pack_kernel<<<(BB*TT*PIX + 255) / 256, 256>>>(masks);

    // 1: masked pool
    dim3 grid1(TT*BB, CC/CG);
    pool_kernel<<<grid1, 256>>>(x);

    // 2: GCN chain
    gcn_kernel<<<BB, 192>>>(W_emb, W_gcn, b_gcn);

    // 3: residual scatter + add
    dim3 grid3(TT*BB, CC/CG);
    scatter_kernel<<<grid3, 256>>>(x, out);
}

// round 2
// speedup vs baseline: 1.0216x; 1.0216x over previous
#include <cuda_runtime.h>
#include <cuda_bf16.h>
#include <stdint.h>

// Problem constants
#define TT 6
#define BB 8
#define CC 192
#define HH 112
#define WW 112
#define KK 3
#define H0 56
#define W0 56
#define HWPIX (HH*WW)          // 12544
#define PIX (H0*W0)            // 3136
#define NN (TT*KK)             // 18 nodes
#define CG 8                   // channels per block in streaming kernels

// Scratch (static device globals — no allocation)
__device__ float g_feat[BB*NN*CC];          // node features [B][N=T*K][C]
__device__ float g_outk[BB*NN*CC];          // GCN output    [B][N=T*K][C]

// ---------------------------------------------------------------------------
// Kernel 1: masked adaptive pooling.
// feat[b,t,k,c] = sum_{h,w} x[t,b,c,h,w] * mask[b,t,k,h/2,w/2] / (H*W)
// block = (t*B+b, channel-group of CG=8), 256 threads.
// Masks decoded ONCE per block into 3 float smem planes; channel loop inner
// so the mask loads amortize over 8 channels.
__global__ __launch_bounds__(256) void pool_kernel(const float* __restrict__ x,
                                                   const int* __restrict__ masks) {
    int tb = blockIdx.x;          // t*B + b
    int cg = blockIdx.y;          // channel group
    int t = tb / BB, b = tb % BB;

    __shared__ float mf[3][PIX];      // 37.6 KB
    __shared__ float red_s[8][24];

    const int* mp = masks + ((size_t)(b*TT + t) * KK) * PIX;
    for (int i = threadIdx.x; i < PIX; i += 256) {
        mf[0][i] = (float)(mp[i] & 1);
        mf[1][i] = (float)(mp[PIX + i] & 1);
        mf[2][i] = (float)(mp[2*PIX + i] & 1);
    }
    __syncthreads();

    const float* xbase = x + ((size_t)(t*BB + b)*CC + cg*CG) * HWPIX;

    float acc[CG][3];
    #pragma unroll
    for (int cc = 0; cc < CG; cc++) {
        acc[cc][0] = 0.f; acc[cc][1] = 0.f; acc[cc][2] = 0.f;
    }

    for (int i4 = threadIdx.x; i4 < HWPIX/4; i4 += 256) {
        int lin = i4 * 4;
        int h = lin / WW;
        int w = lin - h * WW;                 // multiple of 4 -> (w>>1) even
        int mb = (h >> 1) * W0 + (w >> 1);    // always even
        float2 m0 = *(const float2*)&mf[0][mb];
        float2 m1 = *(const float2*)&mf[1][mb];
        float2 m2 = *(const float2*)&mf[2][mb];
        #pragma unroll
        for (int cc = 0; cc < CG; cc++) {
            float4 v = *(const float4*)(xbase + (size_t)cc*HWPIX + lin);
            float p0 = v.x + v.y, p1 = v.z + v.w;
            acc[cc][0] += p0 * m0.x + p1 * m0.y;
            acc[cc][1] += p0 * m1.x + p1 * m1.y;
            acc[cc][2] += p0 * m2.x + p1 * m2.y;
        }
    }

    // reduce 24 values across the block
    int warp = threadIdx.x >> 5, lane = threadIdx.x & 31;
    #pragma unroll
    for (int cc = 0; cc < CG; cc++) {
        #pragma unroll
        for (int k = 0; k < 3; k++) {
            float s = acc[cc][k];
            #pragma unroll
            for (int off = 16; off; off >>= 1)
                s += __shfl_down_sync(0xFFFFFFFFu, s, off);
            if (lane == 0) red_s[warp][cc*3 + k] = s;
        }
    }
    __syncthreads();
    if (threadIdx.x < 24) {
        float s = 0.f;
        #pragma unroll
        for (int w8 = 0; w8 < 8; w8++) s += red_s[w8][threadIdx.x];
        int cc = threadIdx.x / 3, k = threadIdx.x % 3;
        int c = cg * CG + cc;
        // layout [B][T][K][C] == [B][N][C] with n = t*K + k
        g_feat[((size_t)(b*TT + t) * KK + k) * CC + c] = s * (1.0f / (float)HWPIX);
    }
}

// ---------------------------------------------------------------------------
// Kernel 2: the GCN chain per batch. 8 blocks x 384 threads.
// Warps 0-5 and 6-11 run independent stages concurrently:
//   phase A: {aaa = node W_emb^T} || {gram = node node^T}
//   phase B: {sup = aaa W_gcn}    || {softmax rows of gram}
//   phase C: out = adj sup + b_gcn
__global__ __launch_bounds__(384) void gcn_kernel(const float* __restrict__ W_emb,
                                                  const float* __restrict__ W_gcn,
                                                  const float* __restrict__ b_gcn) {
    const int LD = 193;  // padded row stride (conflict-free)
    __shared__ float node_s[NN*LD];
    __shared__ float aaa_s[NN*LD];
    __shared__ float sup_s[NN*LD];
    __shared__ float adj_s[NN*NN];

    int b = blockIdx.x;
    int tid = threadIdx.x;     // 0..383

    const float* fb = g_feat + (size_t)b * NN * CC;
    for (int j = tid; j < NN*CC; j += 384)
        node_s[(j / CC) * LD + (j % CC)] = fb[j];
    __syncthreads();

    // ---- Phase A ----
    if (tid < 192) {
        int d = tid;
        float acc[NN];
        #pragma unroll
        for (int n = 0; n < NN; n++) acc[n] = 0.f;
        const float* wr = W_emb + (size_t)d * CC;
        for (int c = 0; c < CC; c++) {
            float w = __ldg(&wr[c]);
            #pragma unroll
            for (int n = 0; n < NN; n++) acc[n] += node_s[n*LD + c] * w;
        }
        #pragma unroll
        for (int n = 0; n < NN; n++) aaa_s[n*LD + d] = acc[n];
    } else {
        for (int p = tid - 192; p < NN*NN; p += 192) {
            int n = p / NN, m = p % NN;
            float s = 0.f;
            #pragma unroll 4
            for (int c = 0; c < CC; c++)
                s += node_s[n*LD + c] * node_s[m*LD + c];
            adj_s[p] = s;
        }
    }
    __syncthreads();

    // ---- Phase B ----
    if (tid < 192) {
        int d = tid;
        float acc[NN];
        #pragma unroll
        for (int m = 0; m < NN; m++) acc[m] = 0.f;
        for (int d2 = 0; d2 < CC; d2++) {
            float w = __ldg(&W_gcn[(size_t)d2 * CC + d]);
            #pragma unroll
            for (int m = 0; m < NN; m++) acc[m] += aaa_s[m*LD + d2] * w;
        }
        #pragma unroll
        for (int m = 0; m < NN; m++) sup_s[m*LD + d] = acc[m];
    } else if (tid - 192 < NN) {
        int n = tid - 192;
        float mx = -1e30f;
        #pragma unroll
        for (int m = 0; m < NN; m++) mx = fmaxf(mx, adj_s[n*NN + m]);
        float e[NN]; float sm = 0.f;
        #pragma unroll
        for (int m = 0; m < NN; m++) { e[m] = expf(adj_s[n*NN + m] - mx); sm += e[m]; }
        float inv = 1.0f / sm;
        #pragma unroll
        for (int m = 0; m < NN; m++) adj_s[n*NN + m] = e[m] * inv;
    }
    __syncthreads();

    // ---- Phase C ----
    if (tid < 192) {
        int d = tid;
        float bg = __ldg(&b_gcn[d]);
        #pragma unroll
        for (int n = 0; n < NN; n++) {
            float o = bg;
            #pragma unroll
            for (int m = 0; m < NN; m++) o += adj_s[n*NN + m] * sup_s[m*LD + d];
            g_outk[((size_t)b * NN + n) * CC + d] = o;
        }
    }
}

// ---------------------------------------------------------------------------
// Kernel 3: residual scatter + add.
// out[t,b,c,h,w] = x[t,b,c,h,w] + sum_k outk[b,t,k,c] * mask[b,t,k,h/2,w/2]
// Same structure as pool: float mask planes in smem, channel-inner loop.
__global__ __launch_bounds__(256) void scatter_kernel(const float* __restrict__ x,
                                                      const int* __restrict__ masks,
                                                      float* __restrict__ out) {
    int tb = blockIdx.x;          // t*B + b
    int cg = blockIdx.y;
    int t = tb / BB, b = tb % BB;

    __shared__ float mf[3][PIX];
    __shared__ float rs[CG][3];

    const int* mp = masks + ((size_t)(b*TT + t) * KK) * PIX;
    for (int i = threadIdx.x; i < PIX; i += 256) {
        mf[0][i] = (float)(mp[i] & 1);
        mf[1][i] = (float)(mp[PIX + i] & 1);
        mf[2][i] = (float)(mp[2*PIX + i] & 1);
    }
    if (threadIdx.x < CG*3) {
        int cc = threadIdx.x / 3, k = threadIdx.x % 3;
        rs[cc][k] = g_outk[((size_t)(b*TT + t) * KK + k) * CC + cg*CG + cc];
    }
    __syncthreads();

    float r[CG][3];
    #pragma unroll
    for (int cc = 0; cc < CG; cc++) {
        r[cc][0] = rs[cc][0]; r[cc][1] = rs[cc][1]; r[cc][2] = rs[cc][2];
    }

    size_t plane0 = ((size_t)(t*BB + b)*CC + cg*CG) * HWPIX;
    const float* xbase = x + plane0;
    float*       obase = out + plane0;

    for (int i4 = threadIdx.x; i4 < HWPIX/4; i4 += 256) {
        int lin = i4 * 4;
        int h = lin / WW;
        int w = lin - h * WW;
        int mb = (h >> 1) * W0 + (w >> 1);
        float2 m0 = *(const float2*)&mf[0][mb];
        float2 m1 = *(const float2*)&mf[1][mb];
        float2 m2 = *(const float2*)&mf[2][mb];
        #pragma unroll
        for (int cc = 0; cc < CG; cc++) {
            float4 v = *(const float4*)(xbase + (size_t)cc*HWPIX + lin);
            float c0 = r[cc][0]*m0.x + r[cc][1]*m1.x + r[cc][2]*m2.x;
            float c1 = r[cc][0]*m0.y + r[cc][1]*m1.y + r[cc][2]*m2.y;
            float4 o;
            o.x = v.x + c0; o.y = v.y + c0;
            o.z = v.z + c1; o.w = v.w + c1;
            *(float4*)(obase + (size_t)cc*HWPIX + lin) = o;
        }
    }
}

// ---------------------------------------------------------------------------
extern "C" void kernel_launch(void* const* d_in, const int* in_sizes, int n_in,
                              void* d_out, int out_size) {
    const float* x      = (const float*)d_in[0];
    const int*   masks  = (const int*)  d_in[1];
    const float* W_emb  = (const float*)d_in[2];
    const float* W_gcn  = (const float*)d_in[3];
    const float* b_gcn  = (const float*)d_in[4];
    float* out = (float*)d_out;

    dim3 grid(TT*BB, CC/CG);
    pool_kernel<<<grid, 256>>>(x, masks);
    gcn_kernel<<<BB, 384>>>(W_emb, W_gcn, b_gcn);
    scatter_kernel<<<grid, 256>>>(x, masks, out);
}

// round 3
// speedup vs baseline: 1.1704x; 1.1456x over previous
#include <cuda_runtime.h>
#include <cuda_bf16.h>
#include <stdint.h>

// Problem constants
#define TT 6
#define BB 8
#define CC 192
#define HH 112
#define WW 112
#define KK 3
#define H0 56
#define W0 56
#define HWPIX (HH*WW)          // 12544
#define PIX (H0*W0)            // 3136
#define NN (TT*KK)             // 18 nodes
#define CG 8                   // channels per block in streaming kernels

// Scratch (static device globals — no allocation)
__device__ float g_feat[BB*NN*CC];          // node features [B][N=T*K][C]
__device__ float g_outk[BB*NN*CC];          // GCN output    [B][N][C]
__device__ float g_Wc[CC*CC];               // W_emb^T @ W_gcn
__device__ float g_adj[BB*NN*NN];           // softmaxed adjacency
__device__ float g_sup[BB*NN*CC];           // node @ Wc

// ---------------------------------------------------------------------------
// Kernel 1: masked adaptive pooling (at HBM ceiling — unchanged from R2).
__global__ __launch_bounds__(256) void pool_kernel(const float* __restrict__ x,
                                                   const int* __restrict__ masks) {
    int tb = blockIdx.x;          // t*B + b
    int cg = blockIdx.y;          // channel group
    int t = tb / BB, b = tb % BB;

    __shared__ float mf[3][PIX];
    __shared__ float red_s[8][24];

    const int* mp = masks + ((size_t)(b*TT + t) * KK) * PIX;
    for (int i = threadIdx.x; i < PIX; i += 256) {
        mf[0][i] = (float)(mp[i] & 1);
        mf[1][i] = (float)(mp[PIX + i] & 1);
        mf[2][i] = (float)(mp[2*PIX + i] & 1);
    }
    __syncthreads();

    const float* xbase = x + ((size_t)(t*BB + b)*CC + cg*CG) * HWPIX;

    float acc[CG][3];
    #pragma unroll
    for (int cc = 0; cc < CG; cc++) {
        acc[cc][0] = 0.f; acc[cc][1] = 0.f; acc[cc][2] = 0.f;
    }

    for (int i4 = threadIdx.x; i4 < HWPIX/4; i4 += 256) {
        int lin = i4 * 4;
        int h = lin / WW;
        int w = lin - h * WW;
        int mb = (h >> 1) * W0 + (w >> 1);
        float2 m0 = *(const float2*)&mf[0][mb];
        float2 m1 = *(const float2*)&mf[1][mb];
        float2 m2 = *(const float2*)&mf[2][mb];
        #pragma unroll
        for (int cc = 0; cc < CG; cc++) {
            float4 v = *(const float4*)(xbase + (size_t)cc*HWPIX + lin);
            float p0 = v.x + v.y, p1 = v.z + v.w;
            acc[cc][0] += p0 * m0.x + p1 * m0.y;
            acc[cc][1] += p0 * m1.x + p1 * m1.y;
            acc[cc][2] += p0 * m2.x + p1 * m2.y;
        }
    }

    int warp = threadIdx.x >> 5, lane = threadIdx.x & 31;
    #pragma unroll
    for (int cc = 0; cc < CG; cc++) {
        #pragma unroll
        for (int k = 0; k < 3; k++) {
            float s = acc[cc][k];
            #pragma unroll
            for (int off = 16; off; off >>= 1)
                s += __shfl_down_sync(0xFFFFFFFFu, s, off);
            if (lane == 0) red_s[warp][cc*3 + k] = s;
        }
    }
    __syncthreads();
    if (threadIdx.x < 24) {
        float s = 0.f;
        #pragma unroll
        for (int w8 = 0; w8 < 8; w8++) s += red_s[w8][threadIdx.x];
        int cc = threadIdx.x / 3, k = threadIdx.x % 3;
        int c = cg * CG + cc;
        g_feat[((size_t)(b*TT + t) * KK + k) * CC + c] = s * (1.0f / (float)HWPIX);
    }
}

// ---------------------------------------------------------------------------
// GCN kernel A: Wc[c][e] = sum_d W_emb[d][c] * W_gcn[d][e]
// 192 blocks (c) x 192 threads (e); W_gcn reads coalesced, W_emb column in smem.
__global__ __launch_bounds__(192) void wc_kernel(const float* __restrict__ W_emb,
                                                 const float* __restrict__ W_gcn) {
    __shared__ float col[CC];
    int c = blockIdx.x, e = threadIdx.x;
    if (threadIdx.x < CC) col[threadIdx.x] = W_emb[(size_t)threadIdx.x * CC + c];
    __syncthreads();
    float acc = 0.f;
    #pragma unroll 8
    for (int d = 0; d < CC; d++)
        acc += col[d] * __ldg(&W_gcn[(size_t)d * CC + e]);
    g_Wc[c*CC + e] = acc;
}

// ---------------------------------------------------------------------------
// GCN kernel S: per (n, b) block — gram row + softmax -> g_adj row,
// and sup row = node_n @ Wc -> g_sup. grid (NN, BB) x 192 threads.
__global__ __launch_bounds__(192) void gcn_s_kernel() {
    __shared__ float node_s[NN*CC];
    __shared__ float dots[NN];

    int n = blockIdx.x, b = blockIdx.y;
    int tid = threadIdx.x;
    int warp = tid >> 5, lane = tid & 31;

    const float* fb = g_feat + (size_t)b * NN * CC;
    for (int j = tid; j < NN*CC; j += 192)
        node_s[j] = fb[j];
    __syncthreads();

    // gram row: warp w handles m = w*3 + q (6 warps x 3 = 18)
    #pragma unroll
    for (int q = 0; q < 3; q++) {
        int m = warp * 3 + q;
        float s = 0.f;
        #pragma unroll
        for (int j = 0; j < 6; j++) {
            int c = lane + 32*j;
            s += node_s[n*CC + c] * node_s[m*CC + c];
        }
        #pragma unroll
        for (int off = 16; off; off >>= 1)
            s += __shfl_down_sync(0xFFFFFFFFu, s, off);
        if (lane == 0) dots[m] = s;
    }
    __syncthreads();

    if (tid == 0) {
        float mx = -1e30f;
        #pragma unroll
        for (int m = 0; m < NN; m++) mx = fmaxf(mx, dots[m]);
        float sm = 0.f;
        #pragma unroll
        for (int m = 0; m < NN; m++) { float e = expf(dots[m] - mx); dots[m] = e; sm += e; }
        float inv = 1.0f / sm;
        #pragma unroll
        for (int m = 0; m < NN; m++) dots[m] *= inv;
    }
    __syncthreads();
    if (tid < NN) g_adj[((size_t)b*NN + n)*NN + tid] = dots[tid];

    // sup row: sup[e] = sum_c node_n[c] * Wc[c][e]  (Wc coalesced)
    float acc = 0.f;
    const float* nrow = node_s + n*CC;
    #pragma unroll 4
    for (int c = 0; c < CC; c++)
        acc += nrow[c] * g_Wc[c*CC + tid];
    g_sup[((size_t)b*NN + n)*CC + tid] = acc;
}

// ---------------------------------------------------------------------------
// GCN kernel O: out[b][n][e] = b_gcn[e] + sum_m adj[n][m] * sup[b][m][e]
// grid (NN, BB) x 192 threads.
__global__ __launch_bounds__(192) void gcn_o_kernel(const float* __restrict__ b_gcn) {
    __shared__ float arow[NN];
    int n = blockIdx.x, b = blockIdx.y;
    int e = threadIdx.x;
    if (threadIdx.x < NN)
        arow[threadIdx.x] = g_adj[((size_t)b*NN + n)*NN + threadIdx.x];
    __syncthreads();
    float acc = __ldg(&b_gcn[e]);
    #pragma unroll
    for (int m = 0; m < NN; m++)
        acc += arow[m] * g_sup[((size_t)b*NN + m)*CC + e];
    g_outk[((size_t)b*NN + n)*CC + e] = acc;
}

// ---------------------------------------------------------------------------
// Kernel 3: residual scatter + add (at HBM ceiling — unchanged from R2).
__global__ __launch_bounds__(256) void scatter_kernel(const float* __restrict__ x,
                                                      const int* __restrict__ masks,
                                                      float* __restrict__ out) {
    int tb = blockIdx.x;
    int cg = blockIdx.y;
    int t = tb / BB, b = tb % BB;

    __shared__ float mf[3][PIX];
    __shared__ float rs[CG][3];

    const int* mp = masks + ((size_t)(b*TT + t) * KK) * PIX;
    for (int i = threadIdx.x; i < PIX; i += 256) {
        mf[0][i] = (float)(mp[i] & 1);
        mf[1][i] = (float)(mp[PIX + i] & 1);
        mf[2][i] = (float)(mp[2*PIX + i] & 1);
    }
    if (threadIdx.x < CG*3) {
        int cc = threadIdx.x / 3, k = threadIdx.x % 3;
        rs[cc][k] = g_outk[((size_t)(b*TT + t) * KK + k) * CC + cg*CG + cc];
    }
    __syncthreads();

    float r[CG][3];
    #pragma unroll
    for (int cc = 0; cc < CG; cc++) {
        r[cc][0] = rs[cc][0]; r[cc][1] = rs[cc][1]; r[cc][2] = rs[cc][2];
    }

    size_t plane0 = ((size_t)(t*BB + b)*CC + cg*CG) * HWPIX;
    const float* xbase = x + plane0;
    float*       obase = out + plane0;

    for (int i4 = threadIdx.x; i4 < HWPIX/4; i4 += 256) {
        int lin = i4 * 4;
        int h = lin / WW;
        int w = lin - h * WW;
        int mb = (h >> 1) * W0 + (w >> 1);
        float2 m0 = *(const float2*)&mf[0][mb];
        float2 m1 = *(const float2*)&mf[1][mb];
        float2 m2 = *(const float2*)&mf[2][mb];
        #pragma unroll
        for (int cc = 0; cc < CG; cc++) {
            float4 v = *(const float4*)(xbase + (size_t)cc*HWPIX + lin);
            float c0 = r[cc][0]*m0.x + r[cc][1]*m1.x + r[cc][2]*m2.x;
            float c1 = r[cc][0]*m0.y + r[cc][1]*m1.y + r[cc][2]*m2.y;
            float4 o;
            o.x = v.x + c0; o.y = v.y + c0;
            o.z = v.z + c1; o.w = v.w + c1;
            *(float4*)(obase + (size_t)cc*HWPIX + lin) = o;
        }
    }
}

// ---------------------------------------------------------------------------
extern "C" void kernel_launch(void* const* d_in, const int* in_sizes, int n_in,
                              void* d_out, int out_size) {
    const float* x      = (const float*)d_in[0];
    const int*   masks  = (const int*)  d_in[1];
    const float* W_emb  = (const float*)d_in[2];
    const float* W_gcn  = (const float*)d_in[3];
    const float* b_gcn  = (const float*)d_in[4];
    float* out = (float*)d_out;

    dim3 grid(TT*BB, CC/CG);
    dim3 gnb(NN, BB);

    wc_kernel<<<CC, 192>>>(W_emb, W_gcn);        // independent of pool
    pool_kernel<<<grid, 256>>>(x, masks);
    gcn_s_kernel<<<gnb, 192>>>();
    gcn_o_kernel<<<gnb, 192>>>(b_gcn);
    scatter_kernel<<<grid, 256>>>(x, masks, out);
}